// round 5
// baseline (speedup 1.0000x reference)
#include <cuda_runtime.h>

// ---------------------------------------------------------------------------
// LLG micromagnetics RK4 solver, persistent-kernel formulation.
// Grid: 256x256 cells, 3-component magnetization.
// 100 relax steps (alpha=0.5) + 2 signals x 256 driven steps (alpha=0.01).
// One thread per cell (128 blocks x 512 threads = 65536). State held in
// registers; stage field ping-pongs through two L2-resident device buffers.
// Grid-wide software barrier between RK4 substages (4 per step).
// ---------------------------------------------------------------------------

namespace {
constexpr int NXC    = 256;
constexpr int NYC    = 256;
constexpr int NCELL  = NXC * NYC;     // 65536
constexpr int NBLK   = 128;
constexpr int NTHR   = 512;           // NBLK*NTHR == NCELL
constexpr int TSTEPS = 256;
constexpr int NSRC   = 3;
constexpr int NPROBE = 5;
constexpr int NSIG   = 2;
constexpr int RELAX  = 100;

constexpr double GAMMA_LL = 175950000000.0;
constexpr double DT       = 5e-12;
constexpr double A_EXCH   = 3.5e-12;
constexpr double DX       = 5e-08;
constexpr double MU0      = 1.2566370614359172e-06; // 4e-7*pi
constexpr float  CSOT     = 1e-4f;
constexpr float  HSTEP    = (float)(GAMMA_LL * DT);     // 0.87975
}

__device__ float    g_stage[2][3][NCELL];
__device__ unsigned g_bar_count;
__device__ unsigned g_bar_gen;
__device__ int      g_zero_int = 0;

// ---------------------------------------------------------------------------
// Software grid barrier (all NBLK blocks guaranteed co-resident: 128 blocks,
// 512 thr, 1 block/SM on a 148-SM chip).
// ---------------------------------------------------------------------------
__device__ __forceinline__ void grid_sync() {
    __threadfence();          // release: make this thread's stage stores visible
    __syncthreads();
    if (threadIdx.x == 0) {
        unsigned gen = atomicAdd(&g_bar_gen, 0u);   // read generation BEFORE arriving
        unsigned t   = atomicAdd(&g_bar_count, 1u);
        if (t == NBLK - 1u) {
            atomicExch(&g_bar_count, 0u);
            __threadfence();                        // reset visible before release
            atomicAdd(&g_bar_gen, 1u);
        } else {
            while (atomicAdd(&g_bar_gen, 0u) == gen) { __nanosleep(64); }
        }
    }
    __syncthreads();
    __threadfence();          // acquire: subsequent loads see peers' stores
}

// ---------------------------------------------------------------------------
// One torque evaluation at this thread's cell. Stage field read from
// g_stage[cur] (neighbors, L2 via __ldcg); self value passed in registers.
// ---------------------------------------------------------------------------
__device__ __forceinline__ void stage_eval(
    int cur, int iU, int iD, int iL, int iR,
    float sx, float sy, float sz,
    float Bex, float Bey, float Bez,
    float cex, float dzf, float negInv, float alpha,
    float& kx, float& ky, float& kz)
{
    const float* px = &g_stage[cur][0][0];
    const float* py = &g_stage[cur][1][0];
    const float* pz = &g_stage[cur][2][0];

    float lx = __ldcg(px + iU) + __ldcg(px + iD) + __ldcg(px + iL) + __ldcg(px + iR) - 4.0f * sx;
    float ly = __ldcg(py + iU) + __ldcg(py + iD) + __ldcg(py + iL) + __ldcg(py + iR) - 4.0f * sy;
    float lz = __ldcg(pz + iU) + __ldcg(pz + iD) + __ldcg(pz + iL) + __ldcg(pz + iR) - 4.0f * sz;

    float Bx = Bex + cex * lx;
    float By = Bey + cex * ly;
    float Bz = Bez + cex * lz + dzf * sz;    // demag acts on z only

    // c1 = m x Beff
    float c1x = sy * Bz - sz * By;
    float c1y = sz * Bx - sx * Bz;
    float c1z = sx * By - sy * Bx;
    // c2 = m x c1
    float c2x = sy * c1z - sz * c1y;
    float c2y = sz * c1x - sx * c1z;
    float c2z = sx * c1y - sy * c1x;
    // sot = CSOT * m x (m x p), p = (0,1,0)  =>  (mx*my, -(mx^2+mz^2), my*mz)
    kx = negInv * (c1x + alpha * c2x) + CSOT * (sx * sy);
    ky = negInv * (c1y + alpha * c2y) - CSOT * (sx * sx + sz * sz);
    kz = negInv * (c1z + alpha * c2z) + CSOT * (sy * sz);
}

__device__ __forceinline__ void store_stage(int buf, int cell, float x, float y, float z) {
    __stcg(&g_stage[buf][0][cell], x);
    __stcg(&g_stage[buf][1][cell], y);
    __stcg(&g_stage[buf][2][cell], z);
}

// ---------------------------------------------------------------------------
// One full RK4 step. On entry: g_stage[cur] holds the current field m, and
// (mx,my,mz) registers equal this cell's m. On exit: same invariant for m_new.
// ---------------------------------------------------------------------------
__device__ __forceinline__ void rk4_step(
    int& cur, int cell, int iU, int iD, int iL, int iR,
    float& mx, float& my, float& mz,
    float Bex, float Bey, float Bez,
    float cex, float dzf, float negInv, float alpha)
{
    const float h  = HSTEP;
    const float h2 = 0.5f * HSTEP;
    const float h6 = HSTEP / 6.0f;

    float kx, ky, kz, ax, ay, az, sx, sy, sz;

    // --- k1 ---
    stage_eval(cur, iU, iD, iL, iR, mx, my, mz, Bex, Bey, Bez, cex, dzf, negInv, alpha, kx, ky, kz);
    ax = kx; ay = ky; az = kz;
    sx = mx + h2 * kx; sy = my + h2 * ky; sz = mz + h2 * kz;
    store_stage(cur ^ 1, cell, sx, sy, sz);
    grid_sync(); cur ^= 1;

    // --- k2 ---
    stage_eval(cur, iU, iD, iL, iR, sx, sy, sz, Bex, Bey, Bez, cex, dzf, negInv, alpha, kx, ky, kz);
    ax += 2.0f * kx; ay += 2.0f * ky; az += 2.0f * kz;
    sx = mx + h2 * kx; sy = my + h2 * ky; sz = mz + h2 * kz;
    store_stage(cur ^ 1, cell, sx, sy, sz);
    grid_sync(); cur ^= 1;

    // --- k3 ---
    stage_eval(cur, iU, iD, iL, iR, sx, sy, sz, Bex, Bey, Bez, cex, dzf, negInv, alpha, kx, ky, kz);
    ax += 2.0f * kx; ay += 2.0f * ky; az += 2.0f * kz;
    sx = mx + h * kx; sy = my + h * ky; sz = mz + h * kz;
    store_stage(cur ^ 1, cell, sx, sy, sz);
    grid_sync(); cur ^= 1;

    // --- k4 + combine ---
    stage_eval(cur, iU, iD, iL, iR, sx, sy, sz, Bex, Bey, Bez, cex, dzf, negInv, alpha, kx, ky, kz);
    ax += kx; ay += ky; az += kz;
    mx = mx + h6 * ax; my = my + h6 * ay; mz = mz + h6 * az;
    store_stage(cur ^ 1, cell, mx, my, mz);
    grid_sync(); cur ^= 1;
}

// ---------------------------------------------------------------------------
__global__ void init_barrier_kernel() {
    g_bar_count = 0u;
    g_bar_gen   = 0u;
}

__global__ void __launch_bounds__(NTHR, 1) mm_solver_kernel(
    const float* __restrict__ sig,        // (NSIG, TSTEPS, NSRC)
    const float* __restrict__ Bext,       // (1, 3, NXC, NYC)
    const float* __restrict__ Msat_p,     // scalar
    const int*   __restrict__ src_pos,    // (NSRC, 2)
    const int*   __restrict__ probe_pos,  // (NPROBE, 2)
    const int*   __restrict__ fb_p,       // scalar
    float*       __restrict__ out)        // (NSIG, TSTEPS, NPROBE)
{
    const int cell = blockIdx.x * NTHR + threadIdx.x;
    const int r = cell >> 8;
    const int c = cell & 255;

    const int iU = (r > 0)       ? cell - NYC : cell;   // edge padding -> self
    const int iD = (r < NXC - 1) ? cell + NYC : cell;
    const int iL = (c > 0)       ? cell - 1   : cell;
    const int iR = (c < NYC - 1) ? cell + 1   : cell;

    const float Msat = *Msat_p;
    const float cex  = (float)(2.0 * A_EXCH) / (Msat * (float)DX * (float)DX);
    const float dzf  = -(float)MU0 * Msat;
    const int   fb   = *fb_p;

    const float bex  = Bext[0 * NCELL + cell];
    const float bey  = Bext[1 * NCELL + cell];
    const float bez0 = Bext[2 * NCELL + cell];

    int src_id = -1;
    #pragma unroll
    for (int k = 0; k < NSRC; k++)
        if (src_pos[2 * k] == r && src_pos[2 * k + 1] == c) src_id = k;
    int probe_id = -1;
    #pragma unroll
    for (int k = 0; k < NPROBE; k++)
        if (probe_pos[2 * k] == r && probe_pos[2 * k + 1] == c) probe_id = k;

    // initial m = (0, 1, 0)
    float mx = 0.0f, my = 1.0f, mz = 0.0f;
    int cur = 0;
    store_stage(cur, cell, mx, my, mz);
    grid_sync();

    // ---- relaxation: alpha = 0.5, no source ----
    {
        const float alpha  = 0.5f;
        const float negInv = -1.0f / (1.0f + alpha * alpha);
        for (int t = 0; t < RELAX; t++)
            rk4_step(cur, cell, iU, iD, iL, iR, mx, my, mz,
                     bex, bey, bez0, cex, dzf, negInv, alpha);
    }

    const float mrx = mx, mry = my, mrz = mz;   // m_relaxed (registers)

    // ---- driven runs: alpha = 0.01, source injection + probes ----
    const float alpha  = 0.01f;
    const float negInv = -1.0f / (1.0f + alpha * alpha);

    for (int s = 0; s < NSIG; s++) {
        if (s > 0) {
            mx = mrx; my = mry; mz = mrz;
            store_stage(cur, cell, mx, my, mz);
            grid_sync();
        }
        for (int t = 0; t < TSTEPS; t++) {
            float bez = bez0;
            if (src_id >= 0)
                bez += sig[(s * TSTEPS + t) * NSRC + src_id];

            rk4_step(cur, cell, iU, iD, iL, iR, mx, my, mz,
                     bex, bey, bez, cex, dzf, negInv, alpha);

            if (probe_id >= 0) {
                float v = fb ? (mz - mrz) * Msat : mz;
                out[(s * TSTEPS + t) * NPROBE + probe_id] = v;
            }
        }
    }
}

// ---------------------------------------------------------------------------
extern "C" void kernel_launch(void* const* d_in, const int* in_sizes, int n_in,
                              void* d_out, int out_size) {
    (void)in_sizes; (void)out_size;
    const float* sig     = (const float*)d_in[0];
    const float* Bext    = (const float*)d_in[1];
    const float* Msat_p  = (const float*)d_in[2];
    const int*   srcp    = (const int*)d_in[3];
    const int*   probep  = (const int*)d_in[4];
    const int*   fbp;
    if (n_in > 5) {
        fbp = (const int*)d_in[5];
    } else {
        void* p = nullptr;
        cudaGetSymbolAddress(&p, g_zero_int);
        fbp = (const int*)p;
    }
    float* out = (float*)d_out;

    init_barrier_kernel<<<1, 1>>>();
    mm_solver_kernel<<<NBLK, NTHR>>>(sig, Bext, Msat_p, srcp, probep, fbp, out);
}

// round 7
// speedup vs baseline: 2.9379x; 2.9379x over previous
#include <cuda_runtime.h>

// ---------------------------------------------------------------------------
// LLG micromagnetics RK4 solver — halo-redundant tiled persistent kernel.
//
// 256x256 grid, 3-component m. 100 relax steps (alpha=0.5) + 2 x 256 driven
// steps (alpha=0.01). 128 blocks (16x8), each owns a 16x32 tile and processes
// a 24x40 region (halo 4 = full RK4 dependency radius). All 4 RK4 substages
// run block-locally in shared memory (__syncthreads only). Inter-block sync
// is an 8-neighbor flag handshake per full step (no global barrier), with
// double-buffered global m so +/-1-step skew between neighbors is safe.
// ---------------------------------------------------------------------------

namespace {
constexpr int NXC   = 256;
constexpr int NYC   = 256;
constexpr int NCELL = NXC * NYC;

constexpr int BGR = 16;             // block-grid rows
constexpr int BGC = 8;              // block-grid cols
constexpr int NBLK = BGR * BGC;     // 128
constexpr int TR  = 16;             // owned tile rows
constexpr int TC  = 32;             // owned tile cols
constexpr int HALO = 4;
constexpr int RH  = TR + 2 * HALO;  // 24
constexpr int RW  = TC + 2 * HALO;  // 40
constexpr int RCELLS = RH * RW;     // 960
constexpr int NTHR = 512;

constexpr int TSTEPS = 256;
constexpr int NSRC   = 3;
constexpr int NPROBE = 5;
constexpr int NSIG   = 2;
constexpr int RELAX  = 100;
constexpr int TOTSTEPS = RELAX + NSIG * TSTEPS;  // 612

constexpr double GAMMA_LL = 175950000000.0;
constexpr double DT       = 5e-12;
constexpr double A_EXCH   = 3.5e-12;
constexpr double DX       = 5e-08;
constexpr double MU0      = 1.2566370614359172e-06;
constexpr float  CSOT     = 1e-4f;
constexpr float  HSTEP    = (float)(GAMMA_LL * DT);   // 0.87975
}

__device__ float    g_m[2][3][NCELL];      // ping-pong field buffers
__device__ float    g_mrel[3][NCELL];      // m_relaxed snapshot
__device__ unsigned g_flags[NBLK];         // per-block step counters
__device__ int      g_zero_int = 0;

// ---------------------------------------------------------------------------
__device__ __forceinline__ void evalk(
    const float* __restrict__ Sx, const float* __restrict__ Sy,
    const float* __restrict__ Sz,
    int u, int d, int l, int r,
    float sx, float sy, float sz,
    float bxv, float byv, float bzv,
    float cex, float dzf, float negInv, float alpha,
    float& kx, float& ky, float& kz)
{
    float lx = Sx[u] + Sx[d] + Sx[l] + Sx[r] - 4.0f * sx;
    float ly = Sy[u] + Sy[d] + Sy[l] + Sy[r] - 4.0f * sy;
    float lz = Sz[u] + Sz[d] + Sz[l] + Sz[r] - 4.0f * sz;

    float Bx = fmaf(cex, lx, bxv);
    float By = fmaf(cex, ly, byv);
    float Bz = fmaf(dzf, sz, fmaf(cex, lz, bzv));

    float c1x = sy * Bz - sz * By;
    float c1y = sz * Bx - sx * Bz;
    float c1z = sx * By - sy * Bx;
    float c2x = sy * c1z - sz * c1y;
    float c2y = sz * c1x - sx * c1z;
    float c2z = sx * c1y - sy * c1x;

    kx = fmaf(negInv, fmaf(alpha, c2x, c1x),  CSOT * (sx * sy));
    ky = fmaf(negInv, fmaf(alpha, c2y, c1y), -CSOT * fmaf(sx, sx, sz * sz));
    kz = fmaf(negInv, fmaf(alpha, c2z, c1z),  CSOT * (sy * sz));
}

// ---------------------------------------------------------------------------
__global__ void init_flags_kernel() {
    if (threadIdx.x < NBLK) g_flags[threadIdx.x] = 0u;
}

__global__ void __launch_bounds__(NTHR, 1) mm_solver_kernel(
    const float* __restrict__ sig,        // (NSIG, TSTEPS, NSRC)
    const float* __restrict__ Bext,       // (1, 3, NXC, NYC)
    const float* __restrict__ Msat_p,
    const int*   __restrict__ src_pos,    // (NSRC, 2)
    const int*   __restrict__ probe_pos,  // (NPROBE, 2)
    const int*   __restrict__ fb_p,
    float*       __restrict__ out)        // (NSIG, TSTEPS, NPROBE)
{
    __shared__ float s_m[3][RCELLS];
    __shared__ float s_a[3][RCELLS];
    __shared__ float s_b[3][RCELLS];

    const int tid = threadIdx.x;
    const int bid = blockIdx.x;
    const int br = bid >> 3, bc = bid & 7;
    const int org_r = br * TR - HALO;
    const int org_c = bc * TC - HALO;

    // ---- neighbor block for this polling thread (tid 0..7) ----
    int nbid = -1;
    if (tid < 8) {
        const int dr8[8] = {-1,-1,-1, 0, 0, 1, 1, 1};
        const int dc8[8] = {-1, 0, 1,-1, 1,-1, 0, 1};
        int nr = br + dr8[tid], ncb = bc + dc8[tid];
        if (nr >= 0 && nr < BGR && ncb >= 0 && ncb < BGC)
            nbid = nr * BGC + ncb;
    }

    const float Msat = *Msat_p;
    const float cex  = (float)(2.0 * A_EXCH) / (Msat * (float)DX * (float)DX);
    const float dzf  = -(float)MU0 * Msat;
    const int   fb   = *fb_p;

    // ---- per-slot (2 region cells / thread) loop-invariant precompute ----
    int  selfN[2], upN[2], dnN[2], lfN[2], rtN[2], gld[2], sid[2], pid[2];
    float bxr[2], byr[2], bz0r[2];
    bool a1[2], a2[2], a3[2], ow[2], vld[2];

    #pragma unroll
    for (int j = 0; j < 2; j++) {
        int idx = tid + j * NTHR;
        bool valid = idx < RCELLS;
        int ii = valid ? idx : 0;
        int lr = ii / RW, lc = ii - lr * RW;
        int gr = org_r + lr, gc = org_c + lc;
        int cr = min(max(gr, 0), NXC - 1);
        int cc = min(max(gc, 0), NYC - 1);
        int ur  = max(cr - 1, 0),       dw  = min(cr + 1, NXC - 1);
        int lcl = max(cc - 1, 0),       rcl = min(cc + 1, NYC - 1);

        selfN[j] = (cr  - org_r) * RW + (cc  - org_c);
        upN[j]   = (ur  - org_r) * RW + (cc  - org_c);
        dnN[j]   = (dw  - org_r) * RW + (cc  - org_c);
        lfN[j]   = (cr  - org_r) * RW + (lcl - org_c);
        rtN[j]   = (cr  - org_r) * RW + (rcl - org_c);
        gld[j]   = cr * NYC + cc;

        bxr[j]  = Bext[0 * NCELL + gld[j]];
        byr[j]  = Bext[1 * NCELL + gld[j]];
        bz0r[j] = Bext[2 * NCELL + gld[j]];

        sid[j] = -1;
        #pragma unroll
        for (int k = 0; k < NSRC; k++)
            if (src_pos[2 * k] == cr && src_pos[2 * k + 1] == cc) sid[j] = k;
        pid[j] = -1;
        #pragma unroll
        for (int k = 0; k < NPROBE; k++)
            if (probe_pos[2 * k] == cr && probe_pos[2 * k + 1] == cc) pid[j] = k;

        a1[j] = valid && lr >= 1 && lr < RH - 1 && lc >= 1 && lc < RW - 1;
        a2[j] = valid && lr >= 2 && lr < RH - 2 && lc >= 2 && lc < RW - 2;
        a3[j] = valid && lr >= 3 && lr < RH - 3 && lc >= 3 && lc < RW - 3;
        ow[j] = valid && lr >= HALO && lr < HALO + TR && lc >= HALO && lc < HALO + TC;
        vld[j] = valid;
    }

    const float H  = HSTEP;
    const float H2 = 0.5f * HSTEP;
    const float H6 = HSTEP / 6.0f;

    float mxr[2], myr[2], mzr[2];
    float ax[2], ay[2], az[2];
    float pmz[2] = {0.0f, 0.0f};

    for (int t = 0; t < TOTSTEPS; ++t) {
        const bool  driven = (t >= RELAX);
        const float alpha  = driven ? 0.01f : 0.5f;
        const float negInv = -1.0f / (1.0f + alpha * alpha);
        const int   rp     = t & 1;

        // ---- wait: 8 neighbors finished step t-1 ----
        if (t > 0) {
            if (nbid >= 0) {
                while ((int)__ldcg(&g_flags[nbid]) < t) { __nanosleep(20); }
            }
            __syncthreads();
            __threadfence();   // acquire: see neighbors' step t-1 stores
        }

        // ---- load region m (registers + smem) ----
        #pragma unroll
        for (int j = 0; j < 2; j++) {
            if (vld[j]) {
                float vx, vy, vz;
                if (t == 0) {
                    vx = 0.0f; vy = 1.0f; vz = 0.0f;            // m0 = (0,1,0)
                } else if (t == RELAX + TSTEPS) {               // signal 1 reset
                    vx = __ldcg(&g_mrel[0][gld[j]]);
                    vy = __ldcg(&g_mrel[1][gld[j]]);
                    vz = __ldcg(&g_mrel[2][gld[j]]);
                } else {
                    vx = __ldcg(&g_m[rp][0][gld[j]]);
                    vy = __ldcg(&g_m[rp][1][gld[j]]);
                    vz = __ldcg(&g_m[rp][2][gld[j]]);
                }
                mxr[j] = vx; myr[j] = vy; mzr[j] = vz;
                int st = tid + j * NTHR;
                s_m[0][st] = vx; s_m[1][st] = vy; s_m[2][st] = vz;
            }
        }

        // ---- per-step effective Bz (source injection) ----
        float bzv[2];
        #pragma unroll
        for (int j = 0; j < 2; j++) {
            bzv[j] = bz0r[j];
            if (driven && sid[j] >= 0)
                bzv[j] += __ldg(&sig[(t - RELAX) * NSRC + sid[j]]);
        }
        __syncthreads();

        // ---- stage 1: k1 from m -> s_a (pad-3 region) ----
        #pragma unroll
        for (int j = 0; j < 2; j++) {
            if (a1[j]) {
                float kx, ky, kz;
                evalk(s_m[0], s_m[1], s_m[2],
                      upN[j], dnN[j], lfN[j], rtN[j],
                      mxr[j], myr[j], mzr[j],
                      bxr[j], byr[j], bzv[j],
                      cex, dzf, negInv, alpha, kx, ky, kz);
                if (ow[j]) { ax[j] = kx; ay[j] = ky; az[j] = kz; }
                int st = tid + j * NTHR;
                s_a[0][st] = fmaf(H2, kx, mxr[j]);
                s_a[1][st] = fmaf(H2, ky, myr[j]);
                s_a[2][st] = fmaf(H2, kz, mzr[j]);
            }
        }
        __syncthreads();

        // ---- stage 2: k2 from s_a -> s_b (pad-2 region) ----
        #pragma unroll
        for (int j = 0; j < 2; j++) {
            if (a2[j]) {
                float sx = s_a[0][selfN[j]], sy = s_a[1][selfN[j]], sz = s_a[2][selfN[j]];
                float kx, ky, kz;
                evalk(s_a[0], s_a[1], s_a[2],
                      upN[j], dnN[j], lfN[j], rtN[j],
                      sx, sy, sz, bxr[j], byr[j], bzv[j],
                      cex, dzf, negInv, alpha, kx, ky, kz);
                if (ow[j]) { ax[j] += 2.0f * kx; ay[j] += 2.0f * ky; az[j] += 2.0f * kz; }
                int st = tid + j * NTHR;
                s_b[0][st] = fmaf(H2, kx, mxr[j]);
                s_b[1][st] = fmaf(H2, ky, myr[j]);
                s_b[2][st] = fmaf(H2, kz, mzr[j]);
            }
        }
        __syncthreads();

        // ---- stage 3: k3 from s_b -> s_a (pad-1 region, full h) ----
        #pragma unroll
        for (int j = 0; j < 2; j++) {
            if (a3[j]) {
                float sx = s_b[0][selfN[j]], sy = s_b[1][selfN[j]], sz = s_b[2][selfN[j]];
                float kx, ky, kz;
                evalk(s_b[0], s_b[1], s_b[2],
                      upN[j], dnN[j], lfN[j], rtN[j],
                      sx, sy, sz, bxr[j], byr[j], bzv[j],
                      cex, dzf, negInv, alpha, kx, ky, kz);
                if (ow[j]) { ax[j] += 2.0f * kx; ay[j] += 2.0f * ky; az[j] += 2.0f * kz; }
                int st = tid + j * NTHR;
                s_a[0][st] = fmaf(H, kx, mxr[j]);
                s_a[1][st] = fmaf(H, ky, myr[j]);
                s_a[2][st] = fmaf(H, kz, mzr[j]);
            }
        }
        __syncthreads();

        // ---- stage 4: k4 from s_a, combine, write global (owned only) ----
        #pragma unroll
        for (int j = 0; j < 2; j++) {
            if (ow[j]) {
                float sx = s_a[0][selfN[j]], sy = s_a[1][selfN[j]], sz = s_a[2][selfN[j]];
                float kx, ky, kz;
                evalk(s_a[0], s_a[1], s_a[2],
                      upN[j], dnN[j], lfN[j], rtN[j],
                      sx, sy, sz, bxr[j], byr[j], bzv[j],
                      cex, dzf, negInv, alpha, kx, ky, kz);
                float nx = fmaf(H6, ax[j] + kx, mxr[j]);
                float ny = fmaf(H6, ay[j] + ky, myr[j]);
                float nz = fmaf(H6, az[j] + kz, mzr[j]);
                int gi = gld[j];   // owned cells: clamp == identity
                __stcg(&g_m[rp ^ 1][0][gi], nx);
                __stcg(&g_m[rp ^ 1][1][gi], ny);
                __stcg(&g_m[rp ^ 1][2][gi], nz);
                if (t == RELAX - 1) {
                    __stcg(&g_mrel[0][gi], nx);
                    __stcg(&g_mrel[1][gi], ny);
                    __stcg(&g_mrel[2][gi], nz);
                    if (pid[j] >= 0) pmz[j] = nz;
                }
                if (driven && pid[j] >= 0) {
                    float v = fb ? (nz - pmz[j]) * Msat : nz;
                    out[(t - RELAX) * NPROBE + pid[j]] = v;
                }
            }
        }

        // ---- publish: flag = t+1 after all stores visible ----
        __threadfence();
        __syncthreads();
        if (tid == 0) atomicExch(&g_flags[bid], (unsigned)(t + 1));
    }
}

// ---------------------------------------------------------------------------
extern "C" void kernel_launch(void* const* d_in, const int* in_sizes, int n_in,
                              void* d_out, int out_size) {
    (void)in_sizes; (void)out_size;
    const float* sig    = (const float*)d_in[0];
    const float* Bext   = (const float*)d_in[1];
    const float* Msat_p = (const float*)d_in[2];
    const int*   srcp   = (const int*)d_in[3];
    const int*   probep = (const int*)d_in[4];
    const int*   fbp;
    if (n_in > 5) {
        fbp = (const int*)d_in[5];
    } else {
        void* p = nullptr;
        cudaGetSymbolAddress(&p, g_zero_int);
        fbp = (const int*)p;
    }
    float* out = (float*)d_out;

    init_flags_kernel<<<1, NBLK>>>();
    mm_solver_kernel<<<NBLK, NTHR>>>(sig, Bext, Msat_p, srcp, probep, fbp, out);
}

// round 11
// speedup vs baseline: 2.9737x; 1.0122x over previous
#include <cuda_runtime.h>

// ---------------------------------------------------------------------------
// LLG micromagnetics RK4 solver — halo-8 fused (2 RK4 steps per inter-block
// sync) tiled persistent kernel.
//
// 256x256 grid. 128 blocks (16x8 block grid), each owns a 16x32 tile and
// processes a 32x48 region (halo 8 = dependency radius of TWO RK4 steps).
// Eight shrinking-pad stages (pads 1..8) advance two full RK4 steps entirely
// block-locally in shared memory. Inter-block sync: 8-neighbor flag
// handshake (st.release.gpu / ld.acquire.gpu) once per fused pair, with
// double-buffered global m (handshake also prevents overwrite-before-read).
// ---------------------------------------------------------------------------

namespace {
constexpr int NXC   = 256;
constexpr int NYC   = 256;
constexpr int NCELL = NXC * NYC;

constexpr int BGR  = 16;
constexpr int BGC  = 8;
constexpr int NBLK = BGR * BGC;      // 128
constexpr int TR   = 16;
constexpr int TC   = 32;
constexpr int HALO = 8;
constexpr int RH   = TR + 2 * HALO;  // 32
constexpr int RW   = TC + 2 * HALO;  // 48
constexpr int RCELLS = RH * RW;      // 1536
constexpr int NTHR = 512;
constexpr int SLOTS = RCELLS / NTHR; // 3 (exact)

constexpr int TSTEPS = 256;
constexpr int NSRC   = 3;
constexpr int NPROBE = 5;
constexpr int NSIG   = 2;
constexpr int RELAX  = 100;
constexpr int TOTSTEPS = RELAX + NSIG * TSTEPS;  // 612
constexpr int FITERS   = TOTSTEPS / 2;           // 306 fused pairs

constexpr double GAMMA_LL = 175950000000.0;
constexpr double DT       = 5e-12;
constexpr double A_EXCH   = 3.5e-12;
constexpr double DX       = 5e-08;
constexpr double MU0      = 1.2566370614359172e-06;
constexpr float  CSOT     = 1e-4f;
constexpr float  HSTEP    = (float)(GAMMA_LL * DT);   // 0.87975
}

__device__ float    g_m[2][3][NCELL];      // ping-pong field buffers
__device__ float    g_mrel[3][NCELL];      // m_relaxed snapshot
__device__ unsigned g_flags[NBLK];         // per-block fused-iter counters
__device__ int      g_zero_int = 0;

// ---------------------------------------------------------------------------
__device__ __forceinline__ void evalk(
    const float* __restrict__ Sx, const float* __restrict__ Sy,
    const float* __restrict__ Sz,
    int u, int d, int l, int r,
    float sx, float sy, float sz,
    float bxv, float byv, float bzvv,
    float cex, float dzf, float negInv, float alpha,
    float& kx, float& ky, float& kz)
{
    float lx = Sx[u] + Sx[d] + Sx[l] + Sx[r] - 4.0f * sx;
    float ly = Sy[u] + Sy[d] + Sy[l] + Sy[r] - 4.0f * sy;
    float lz = Sz[u] + Sz[d] + Sz[l] + Sz[r] - 4.0f * sz;

    float Bx = fmaf(cex, lx, bxv);
    float By = fmaf(cex, ly, byv);
    float Bz = fmaf(dzf, sz, fmaf(cex, lz, bzvv));

    float c1x = sy * Bz - sz * By;
    float c1y = sz * Bx - sx * Bz;
    float c1z = sx * By - sy * Bx;
    float c2x = sy * c1z - sz * c1y;
    float c2y = sz * c1x - sx * c1z;
    float c2z = sx * c1y - sy * c1x;

    kx = fmaf(negInv, fmaf(alpha, c2x, c1x),  CSOT * (sx * sy));
    ky = fmaf(negInv, fmaf(alpha, c2y, c1y), -CSOT * fmaf(sx, sx, sz * sz));
    kz = fmaf(negInv, fmaf(alpha, c2z, c1z),  CSOT * (sy * sz));
}

// ---------------------------------------------------------------------------
__global__ void init_flags_kernel() {
    if (threadIdx.x < NBLK) g_flags[threadIdx.x] = 0u;
}

// Mid stage (pads 1-3 and 5-7): eval from PB, accumulate W*k, store m+COEF*k
// into QB and carry it in sv registers as next stage's self value.
#define STAGE(PAD, PB, QB, COEF, W)                                          \
    _Pragma("unroll")                                                        \
    for (int j = 0; j < SLOTS; ++j) {                                        \
        if (mpad[j] >= (PAD)) {                                              \
            float kx, ky, kz;                                                \
            evalk(PB[0], PB[1], PB[2], uN[j], dN[j], lN[j], rN[j],           \
                  svx[j], svy[j], svz[j], bxv[j], byv[j], bzv[j],            \
                  cex, dzf, negInv, alpha, kx, ky, kz);                      \
            ax[j] = fmaf((W), kx, ax[j]);                                    \
            ay[j] = fmaf((W), ky, ay[j]);                                    \
            az[j] = fmaf((W), kz, az[j]);                                    \
            svx[j] = fmaf((COEF), kx, mx[j]);                                \
            svy[j] = fmaf((COEF), ky, my[j]);                                \
            svz[j] = fmaf((COEF), kz, mz[j]);                                \
            int idx_ = tid + j * NTHR;                                       \
            QB[0][idx_] = svx[j];                                            \
            QB[1][idx_] = svy[j];                                            \
            QB[2][idx_] = svz[j];                                            \
        }                                                                    \
    }                                                                        \
    __syncthreads();

__global__ void __launch_bounds__(NTHR, 1) mm_solver_kernel(
    const float* __restrict__ sig,        // (NSIG, TSTEPS, NSRC) flat
    const float* __restrict__ Bext,       // (1, 3, NXC, NYC)
    const float* __restrict__ Msat_p,
    const int*   __restrict__ src_pos,    // (NSRC, 2)
    const int*   __restrict__ probe_pos,  // (NPROBE, 2)
    const int*   __restrict__ fb_p,
    float*       __restrict__ out)        // (NSIG, TSTEPS, NPROBE) flat
{
    __shared__ float s_m[3][RCELLS];
    __shared__ float s_a[3][RCELLS];
    __shared__ float s_b[3][RCELLS];

    const int tid = threadIdx.x;
    const int bid = blockIdx.x;
    const int br = bid >> 3, bc = bid & 7;
    const int org_r = br * TR - HALO;
    const int org_c = bc * TC - HALO;

    // polling threads 0..7 each own one neighbor block
    int nbid = -1;
    if (tid < 8) {
        const int dr8[8] = {-1,-1,-1, 0, 0, 1, 1, 1};
        const int dc8[8] = {-1, 0, 1,-1, 1,-1, 0, 1};
        int nr = br + dr8[tid], ncb = bc + dc8[tid];
        if (nr >= 0 && nr < BGR && ncb >= 0 && ncb < BGC)
            nbid = nr * BGC + ncb;
    }

    const float Msat = *Msat_p;
    const float cex  = (float)(2.0 * A_EXCH) / (Msat * (float)DX * (float)DX);
    const float dzf  = -(float)MU0 * Msat;
    const int   fb   = *fb_p;

    // ---- per-slot loop-invariant precompute (3 region cells / thread) ----
    int   uN[SLOTS], dN[SLOTS], lN[SLOTS], rN[SLOTS], gld[SLOTS];
    int   mpad[SLOTS], sid[SLOTS], pid[SLOTS];
    float bxv[SLOTS], byv[SLOTS], bz0[SLOTS];

    #pragma unroll
    for (int j = 0; j < SLOTS; ++j) {
        int idx = tid + j * NTHR;                 // 0..1535, always valid
        int lr = idx / RW, lc = idx - lr * RW;
        int gr = org_r + lr, gc = org_c + lc;
        int cr = min(max(gr, 0), NXC - 1);
        int cc = min(max(gc, 0), NYC - 1);
        int ur  = max(cr - 1, 0),  dw  = min(cr + 1, NXC - 1);
        int lcl = max(cc - 1, 0),  rcl = min(cc + 1, NYC - 1);

        uN[j]  = (ur - org_r) * RW + (cc  - org_c);
        dN[j]  = (dw - org_r) * RW + (cc  - org_c);
        lN[j]  = (cr - org_r) * RW + (lcl - org_c);
        rN[j]  = (cr - org_r) * RW + (rcl - org_c);
        gld[j] = cr * NYC + cc;

        bxv[j] = Bext[0 * NCELL + gld[j]];
        byv[j] = Bext[1 * NCELL + gld[j]];
        bz0[j] = Bext[2 * NCELL + gld[j]];

        mpad[j] = min(min(lr, RH - 1 - lr), min(lc, RW - 1 - lc));

        sid[j] = -1;
        #pragma unroll
        for (int k = 0; k < NSRC; k++)
            if (src_pos[2 * k] == cr && src_pos[2 * k + 1] == cc) sid[j] = k;
        pid[j] = -1;
        #pragma unroll
        for (int k = 0; k < NPROBE; k++)
            if (probe_pos[2 * k] == cr && probe_pos[2 * k + 1] == cc) pid[j] = k;
    }

    const float H  = HSTEP;
    const float H2 = 0.5f * HSTEP;
    const float H6 = HSTEP / 6.0f;

    float mx[SLOTS],  my[SLOTS],  mz[SLOTS];
    float ax[SLOTS],  ay[SLOTS],  az[SLOTS];
    float svx[SLOTS], svy[SLOTS], svz[SLOTS];
    float bzv[SLOTS];
    float pz0[SLOTS] = {0.0f, 0.0f, 0.0f};

    for (int fi = 0; fi < FITERS; ++fi) {
        const int   t0     = 2 * fi;
        const bool  driven = (t0 >= RELAX);           // pairs never straddle t=100/356
        const float alpha  = driven ? 0.01f : 0.5f;
        const float negInv = -1.0f / (1.0f + alpha * alpha);
        const int   rp     = fi & 1;

        // ---- wait: all 8 neighbors finished fused iter fi-1 ----
        if (fi > 0) {
            if (nbid >= 0) {
                unsigned v;
                while (true) {
                    asm volatile("ld.acquire.gpu.b32 %0, [%1];"
                                 : "=r"(v) : "l"(&g_flags[nbid]) : "memory");
                    if ((int)v >= fi) break;
                    __nanosleep(20);
                }
            }
            __syncthreads();
        }

        // ---- load region m into registers + s_m ----
        #pragma unroll
        for (int j = 0; j < SLOTS; ++j) {
            int idx = tid + j * NTHR;
            float vx, vy, vz;
            if (t0 == 0) {
                vx = 0.0f; vy = 1.0f; vz = 0.0f;           // m0 = (0,1,0)
            } else if (t0 == RELAX + TSTEPS) {             // signal-1 reset
                vx = __ldcg(&g_mrel[0][gld[j]]);
                vy = __ldcg(&g_mrel[1][gld[j]]);
                vz = __ldcg(&g_mrel[2][gld[j]]);
            } else {
                vx = __ldcg(&g_m[rp][0][gld[j]]);
                vy = __ldcg(&g_m[rp][1][gld[j]]);
                vz = __ldcg(&g_m[rp][2][gld[j]]);
            }
            mx[j] = vx; my[j] = vy; mz[j] = vz;
            svx[j] = vx; svy[j] = vy; svz[j] = vz;
            s_m[0][idx] = vx; s_m[1][idx] = vy; s_m[2][idx] = vz;
        }

        // ---- sub-step A (time step t0): Bz + accumulator init ----
        #pragma unroll
        for (int j = 0; j < SLOTS; ++j) {
            bzv[j] = bz0[j];
            if (driven && sid[j] >= 0)
                bzv[j] += __ldg(&sig[(t0 - RELAX) * NSRC + sid[j]]);
            ax[j] = 0.0f; ay[j] = 0.0f; az[j] = 0.0f;
        }
        __syncthreads();

        STAGE(1, s_m, s_a, H2, 1.0f);     // k1
        STAGE(2, s_a, s_b, H2, 2.0f);     // k2
        STAGE(3, s_b, s_a, H,  2.0f);     // k3

        // stage 4 (pad 4): m_next(t0+1) -> s_m + registers; probes for t0
        #pragma unroll
        for (int j = 0; j < SLOTS; ++j) {
            if (mpad[j] >= 4) {
                float kx, ky, kz;
                evalk(s_a[0], s_a[1], s_a[2], uN[j], dN[j], lN[j], rN[j],
                      svx[j], svy[j], svz[j], bxv[j], byv[j], bzv[j],
                      cex, dzf, negInv, alpha, kx, ky, kz);
                float nx = fmaf(H6, ax[j] + kx, mx[j]);
                float ny = fmaf(H6, ay[j] + ky, my[j]);
                float nz = fmaf(H6, az[j] + kz, mz[j]);
                mx[j] = nx; my[j] = ny; mz[j] = nz;
                svx[j] = nx; svy[j] = ny; svz[j] = nz;
                int idx = tid + j * NTHR;
                s_m[0][idx] = nx; s_m[1][idx] = ny; s_m[2][idx] = nz;
                if (driven && pid[j] >= 0 && mpad[j] >= HALO) {
                    float v = fb ? (nz - pz0[j]) * Msat : nz;
                    out[(t0 - RELAX) * NPROBE + pid[j]] = v;
                }
            }
        }

        // ---- sub-step B (time step t0+1): Bz + accumulator init ----
        #pragma unroll
        for (int j = 0; j < SLOTS; ++j) {
            bzv[j] = bz0[j];
            if (driven && sid[j] >= 0)
                bzv[j] += __ldg(&sig[(t0 + 1 - RELAX) * NSRC + sid[j]]);
            ax[j] = 0.0f; ay[j] = 0.0f; az[j] = 0.0f;
        }
        __syncthreads();

        STAGE(5, s_m, s_a, H2, 1.0f);     // k1
        STAGE(6, s_a, s_b, H2, 2.0f);     // k2
        STAGE(7, s_b, s_a, H,  2.0f);     // k3

        // stage 8 (pad 8 = owned tile): final combine, write global
        #pragma unroll
        for (int j = 0; j < SLOTS; ++j) {
            if (mpad[j] >= HALO) {
                float kx, ky, kz;
                evalk(s_a[0], s_a[1], s_a[2], uN[j], dN[j], lN[j], rN[j],
                      svx[j], svy[j], svz[j], bxv[j], byv[j], bzv[j],
                      cex, dzf, negInv, alpha, kx, ky, kz);
                float nx = fmaf(H6, ax[j] + kx, mx[j]);
                float ny = fmaf(H6, ay[j] + ky, my[j]);
                float nz = fmaf(H6, az[j] + kz, mz[j]);
                int gi = gld[j];                    // owned: clamp == identity
                __stcg(&g_m[rp ^ 1][0][gi], nx);
                __stcg(&g_m[rp ^ 1][1][gi], ny);
                __stcg(&g_m[rp ^ 1][2][gi], nz);
                if (t0 + 1 == RELAX - 1) {          // m_relaxed snapshot (t=99)
                    __stcg(&g_mrel[0][gi], nx);
                    __stcg(&g_mrel[1][gi], ny);
                    __stcg(&g_mrel[2][gi], nz);
                    if (pid[j] >= 0) pz0[j] = nz;
                }
                if (driven && pid[j] >= 0) {
                    float v = fb ? (nz - pz0[j]) * Msat : nz;
                    out[(t0 + 1 - RELAX) * NPROBE + pid[j]] = v;
                }
            }
        }

        // ---- publish fused iter fi complete (release; cumulative over bar) ----
        __syncthreads();
        if (tid == 0) {
            unsigned nf = (unsigned)(fi + 1);
            asm volatile("st.release.gpu.b32 [%0], %1;"
                         :: "l"(&g_flags[bid]), "r"(nf) : "memory");
        }
    }
}

// ---------------------------------------------------------------------------
extern "C" void kernel_launch(void* const* d_in, const int* in_sizes, int n_in,
                              void* d_out, int out_size) {
    (void)in_sizes; (void)out_size;
    const float* sig    = (const float*)d_in[0];
    const float* Bext   = (const float*)d_in[1];
    const float* Msat_p = (const float*)d_in[2];
    const int*   srcp   = (const int*)d_in[3];
    const int*   probep = (const int*)d_in[4];
    const int*   fbp;
    if (n_in > 5) {
        fbp = (const int*)d_in[5];
    } else {
        void* p = nullptr;
        cudaGetSymbolAddress(&p, g_zero_int);
        fbp = (const int*)p;
    }
    float* out = (float*)d_out;

    init_flags_kernel<<<1, NBLK>>>();
    mm_solver_kernel<<<NBLK, NTHR>>>(sig, Bext, Msat_p, srcp, probep, fbp, out);
}